// round 1
// baseline (speedup 1.0000x reference)
#include <cuda_runtime.h>

#define NN 100000
#define NF 512
#define NH 256
#define NC 40
#define ECAP 1700000

// ---------------- scratch (no allocations allowed) ----------------
__device__ float d_XW[(size_t)NN * NH];   // x @ W1            (102.4 MB)
__device__ float d_H [(size_t)NN * NH];   // relu(A·XW + b1)   (102.4 MB)
__device__ float d_HW[(size_t)NN * NC];   // H @ W2            (16 MB)
__device__ int   d_deg[NN];
__device__ int   d_cursor[NN];
__device__ int   d_rowptr[NN + 1];
__device__ int   d_ccol[ECAP];
__device__ float d_cval[ECAP];
__device__ int   d_partials[256];

// ---------------- CSR build ----------------
__global__ void k_hist(const int* __restrict__ erow, int E) {
    int i = blockIdx.x * blockDim.x + threadIdx.x;
    if (i < E) atomicAdd(&d_deg[erow[i]], 1);
}

// exclusive scan of d_deg -> d_rowptr (block-local) + block totals
__global__ void k_scan1() {
    __shared__ int s[512];
    int tid = threadIdx.x;
    int i = blockIdx.x * 512 + tid;
    int v = (i < NN) ? d_deg[i] : 0;
    s[tid] = v;
    __syncthreads();
#pragma unroll
    for (int off = 1; off < 512; off <<= 1) {
        int t = (tid >= off) ? s[tid - off] : 0;
        __syncthreads();
        s[tid] += t;
        __syncthreads();
    }
    if (i < NN) d_rowptr[i] = s[tid] - v;   // exclusive
    if (tid == 511) d_partials[blockIdx.x] = s[511];
}

__global__ void k_scan2(int nb) {
    __shared__ int s[256];
    int tid = threadIdx.x;
    int v = (tid < nb) ? d_partials[tid] : 0;
    s[tid] = v;
    __syncthreads();
#pragma unroll
    for (int off = 1; off < 256; off <<= 1) {
        int t = (tid >= off) ? s[tid - off] : 0;
        __syncthreads();
        s[tid] += t;
        __syncthreads();
    }
    if (tid < nb) d_partials[tid] = s[tid] - v; // exclusive
}

__global__ void k_scan3(int E) {
    int i = blockIdx.x * 512 + threadIdx.x;
    if (i < NN) d_rowptr[i] += d_partials[blockIdx.x];
    if (i == 0) d_rowptr[NN] = E;
}

__global__ void k_scatter(const int* __restrict__ erow, const int* __restrict__ ecol,
                          const float* __restrict__ ev, int E) {
    int i = blockIdx.x * blockDim.x + threadIdx.x;
    if (i >= E) return;
    int r = erow[i];
    int p = d_rowptr[r] + atomicAdd(&d_cursor[r], 1);
    d_ccol[p] = ecol[i];
    d_cval[p] = ev[i];
}

// ---------------- GEMM1: XW = x @ W1   [100000,512]x[512,256] ----------------
// 128x128 block tile, BK=16, 256 threads, 8x8 per-thread register tile.
__global__ __launch_bounds__(256) void k_gemm1(const float* __restrict__ X,
                                               const float* __restrict__ W1,
                                               float* __restrict__ XW) {
    __shared__ float As[16][132];   // transposed A tile, +4 pad
    __shared__ float Bs[16][128];
    int tid = threadIdx.x;
    int tx = tid & 15, ty = tid >> 4;
    int m0 = blockIdx.x * 128;
    int n0 = blockIdx.y * 128;

    int ar = tid >> 2;            // 0..63
    int ac = (tid & 3) * 4;       // 0,4,8,12
    int br = tid >> 5;            // 0..7
    int bc = (tid & 31) * 4;      // 0..124

    float acc[8][8];
#pragma unroll
    for (int i = 0; i < 8; i++)
#pragma unroll
        for (int j = 0; j < 8; j++) acc[i][j] = 0.f;

    for (int k0 = 0; k0 < NF; k0 += 16) {
#pragma unroll
        for (int h = 0; h < 2; h++) {
            int row = m0 + ar + h * 64;
            row = row < NN ? row : NN - 1;      // clamp (garbage rows never stored)
            float4 v = *(const float4*)(X + (size_t)row * NF + k0 + ac);
            As[ac + 0][ar + h * 64] = v.x;
            As[ac + 1][ar + h * 64] = v.y;
            As[ac + 2][ar + h * 64] = v.z;
            As[ac + 3][ar + h * 64] = v.w;
        }
#pragma unroll
        for (int h = 0; h < 2; h++) {
            int kr = br + h * 8;
            *(float4*)&Bs[kr][bc] = *(const float4*)(W1 + (size_t)(k0 + kr) * NH + n0 + bc);
        }
        __syncthreads();
#pragma unroll
        for (int kk = 0; kk < 16; kk++) {
            float a[8], b[8];
            *(float4*)(a)     = *(const float4*)&As[kk][ty * 8];
            *(float4*)(a + 4) = *(const float4*)&As[kk][ty * 8 + 4];
            *(float4*)(b)     = *(const float4*)&Bs[kk][tx * 8];
            *(float4*)(b + 4) = *(const float4*)&Bs[kk][tx * 8 + 4];
#pragma unroll
            for (int i = 0; i < 8; i++)
#pragma unroll
                for (int j = 0; j < 8; j++) acc[i][j] += a[i] * b[j];
        }
        __syncthreads();
    }
#pragma unroll
    for (int i = 0; i < 8; i++) {
        int row = m0 + ty * 8 + i;
        if (row < NN) {
            float* o = XW + (size_t)row * NH + n0 + tx * 8;
            *(float4*)(o)     = make_float4(acc[i][0], acc[i][1], acc[i][2], acc[i][3]);
            *(float4*)(o + 4) = make_float4(acc[i][4], acc[i][5], acc[i][6], acc[i][7]);
        }
    }
}

// ---------------- SpMM1: H = relu(A @ XW + b1), warp per row, 256 feats ----------------
__global__ __launch_bounds__(256) void k_spmm1(const float* __restrict__ XW,
                                               const float* __restrict__ b1,
                                               float* __restrict__ H) {
    int w = (blockIdx.x * blockDim.x + threadIdx.x) >> 5;
    int lane = threadIdx.x & 31;
    if (w >= NN) return;
    int s = d_rowptr[w], e = d_rowptr[w + 1];
    float4 a0 = make_float4(0.f, 0.f, 0.f, 0.f);
    float4 a1 = make_float4(0.f, 0.f, 0.f, 0.f);
    for (int i = s; i < e; i++) {
        int c = d_ccol[i];
        float v = d_cval[i];
        const float4* p = (const float4*)(XW + (size_t)c * NH);
        float4 x0 = p[lane];
        float4 x1 = p[lane + 32];
        a0.x += v * x0.x; a0.y += v * x0.y; a0.z += v * x0.z; a0.w += v * x0.w;
        a1.x += v * x1.x; a1.y += v * x1.y; a1.z += v * x1.z; a1.w += v * x1.w;
    }
    const float4* bb = (const float4*)b1;
    float4 c0 = bb[lane], c1 = bb[lane + 32];
    a0.x = fmaxf(a0.x + c0.x, 0.f); a0.y = fmaxf(a0.y + c0.y, 0.f);
    a0.z = fmaxf(a0.z + c0.z, 0.f); a0.w = fmaxf(a0.w + c0.w, 0.f);
    a1.x = fmaxf(a1.x + c1.x, 0.f); a1.y = fmaxf(a1.y + c1.y, 0.f);
    a1.z = fmaxf(a1.z + c1.z, 0.f); a1.w = fmaxf(a1.w + c1.w, 0.f);
    float4* hp = (float4*)(H + (size_t)w * NH);
    hp[lane]      = a0;
    hp[lane + 32] = a1;
}

// ---------------- GEMM2: HW = H @ W2   [100000,256]x[256,40] ----------------
// thread per row, 40 accumulators, W2 broadcast from smem.
__global__ __launch_bounds__(256) void k_gemm2(const float* __restrict__ H,
                                               const float* __restrict__ W2,
                                               float* __restrict__ HW) {
    __shared__ float w2s[NH * NC];   // 40 KB
    for (int i = threadIdx.x; i < NH * NC; i += 256) w2s[i] = W2[i];
    __syncthreads();
    int r = blockIdx.x * 256 + threadIdx.x;
    if (r >= NN) return;
    float acc[NC];
#pragma unroll
    for (int c = 0; c < NC; c++) acc[c] = 0.f;
    const float4* hp = (const float4*)(H + (size_t)r * NH);
#pragma unroll 4
    for (int k4 = 0; k4 < NH / 4; k4++) {
        float4 h = hp[k4];
        float hv[4] = {h.x, h.y, h.z, h.w};
#pragma unroll
        for (int kk = 0; kk < 4; kk++) {
            const float* wrow = &w2s[(k4 * 4 + kk) * NC];
#pragma unroll
            for (int c4 = 0; c4 < NC / 4; c4++) {
                float4 wv = *(const float4*)(wrow + c4 * 4);
                acc[c4 * 4 + 0] += hv[kk] * wv.x;
                acc[c4 * 4 + 1] += hv[kk] * wv.y;
                acc[c4 * 4 + 2] += hv[kk] * wv.z;
                acc[c4 * 4 + 3] += hv[kk] * wv.w;
            }
        }
    }
    float* o = HW + (size_t)r * NC;
#pragma unroll
    for (int c4 = 0; c4 < NC / 4; c4++)
        *(float4*)(o + c4 * 4) = make_float4(acc[c4 * 4], acc[c4 * 4 + 1],
                                             acc[c4 * 4 + 2], acc[c4 * 4 + 3]);
}

// ---------------- SpMM2: out = A @ HW + b2, warp per row, 40 feats ----------------
__global__ __launch_bounds__(256) void k_spmm2(const float* __restrict__ HW,
                                               const float* __restrict__ b2,
                                               float* __restrict__ out) {
    int w = (blockIdx.x * blockDim.x + threadIdx.x) >> 5;
    int lane = threadIdx.x & 31;
    if (w >= NN) return;
    int s = d_rowptr[w], e = d_rowptr[w + 1];
    float a0 = 0.f, a1 = 0.f;
    for (int i = s; i < e; i++) {
        int c = d_ccol[i];
        float v = d_cval[i];
        const float* p = HW + (size_t)c * NC;
        a0 += v * p[lane];
        if (lane < 8) a1 += v * p[lane + 32];
    }
    float* o = out + (size_t)w * NC;
    o[lane] = a0 + b2[lane];
    if (lane < 8) o[lane + 32] = a1 + b2[lane + 32];
}

// ---------------- launch ----------------
extern "C" void kernel_launch(void* const* d_in, const int* in_sizes, int n_in,
                              void* d_out, int out_size) {
    const float* x   = (const float*)d_in[0];
    const float* W1  = (const float*)d_in[1];
    const float* b1  = (const float*)d_in[2];
    const float* W2  = (const float*)d_in[3];
    const float* b2  = (const float*)d_in[4];
    const int*   er  = (const int*)d_in[5];
    const int*   ec  = (const int*)d_in[6];
    const float* ev  = (const float*)d_in[7];
    int E = in_sizes[5];
    if (E > ECAP) E = ECAP;
    float* out = (float*)d_out;

    void *degp, *curp;
    cudaGetSymbolAddress(&degp, d_deg);
    cudaGetSymbolAddress(&curp, d_cursor);
    cudaMemsetAsync(degp, 0, NN * sizeof(int));
    cudaMemsetAsync(curp, 0, NN * sizeof(int));

    k_hist<<<(E + 511) / 512, 512>>>(er, E);
    int nb = (NN + 511) / 512;   // 196
    k_scan1<<<nb, 512>>>();
    k_scan2<<<1, 256>>>(nb);
    k_scan3<<<nb, 512>>>(E);
    k_scatter<<<(E + 255) / 256, 256>>>(er, ec, ev, E);

    dim3 g1((NN + 127) / 128, NH / 128);
    k_gemm1<<<g1, 256>>>(x, W1, d_XW);
    k_spmm1<<<(NN * 32 + 255) / 256, 256>>>(d_XW, b1, d_H);
    k_gemm2<<<(NN + 255) / 256, 256>>>(d_H, W2, d_HW);
    k_spmm2<<<(NN * 32 + 255) / 256, 256>>>(d_HW, b2, out);
}

// round 2
// speedup vs baseline: 1.0643x; 1.0643x over previous
#include <cuda_runtime.h>
#include <cstdint>

#define NN 100000
#define NF 512
#define NH 256
#define NC 40
#define ECAP 1700000

// ---------------- scratch (no allocations allowed) ----------------
__device__ float d_XW[(size_t)NN * NH];   // x @ W1            (102.4 MB)
__device__ float d_H [(size_t)NN * NH];   // relu(A·XW + b1)   (102.4 MB)
__device__ float d_HW[(size_t)NN * NC];   // H @ W2            (16 MB)
__device__ int   d_deg[NN];
__device__ int   d_cursor[NN];
__device__ int   d_rowptr[NN + 1];
__device__ int   d_ccol[ECAP];
__device__ float d_cval[ECAP];
__device__ int   d_partials[256];

// ---------------- CSR build ----------------
__global__ void k_hist(const int* __restrict__ erow, int E) {
    int i = blockIdx.x * blockDim.x + threadIdx.x;
    if (i < E) atomicAdd(&d_deg[erow[i]], 1);
}

__global__ void k_scan1() {
    __shared__ int s[512];
    int tid = threadIdx.x;
    int i = blockIdx.x * 512 + tid;
    int v = (i < NN) ? d_deg[i] : 0;
    s[tid] = v;
    __syncthreads();
#pragma unroll
    for (int off = 1; off < 512; off <<= 1) {
        int t = (tid >= off) ? s[tid - off] : 0;
        __syncthreads();
        s[tid] += t;
        __syncthreads();
    }
    if (i < NN) d_rowptr[i] = s[tid] - v;   // exclusive
    if (tid == 511) d_partials[blockIdx.x] = s[511];
}

__global__ void k_scan2(int nb) {
    __shared__ int s[256];
    int tid = threadIdx.x;
    int v = (tid < nb) ? d_partials[tid] : 0;
    s[tid] = v;
    __syncthreads();
#pragma unroll
    for (int off = 1; off < 256; off <<= 1) {
        int t = (tid >= off) ? s[tid - off] : 0;
        __syncthreads();
        s[tid] += t;
        __syncthreads();
    }
    if (tid < nb) d_partials[tid] = s[tid] - v; // exclusive
}

__global__ void k_scan3(int E) {
    int i = blockIdx.x * 512 + threadIdx.x;
    if (i < NN) d_rowptr[i] += d_partials[blockIdx.x];
    if (i == 0) d_rowptr[NN] = E;
}

__global__ void k_scatter(const int* __restrict__ erow, const int* __restrict__ ecol,
                          const float* __restrict__ ev, int E) {
    int i = blockIdx.x * blockDim.x + threadIdx.x;
    if (i >= E) return;
    int r = erow[i];
    int p = d_rowptr[r] + atomicAdd(&d_cursor[r], 1);
    d_ccol[p] = ecol[i];
    d_cval[p] = ev[i];
}

// ---------------- GEMM1 (tf32 tensor cores): XW = x @ W1 ----------------
// 128x128 block tile, BK=32, 128 threads (4 warps), warp tile 64x64.
// mma.sync.m16n8k8 tf32. Conflict-free smem: As[128][36], Bs[32][136].
__device__ __forceinline__ uint32_t f2tf32(float f) {
    uint32_t r;
    asm("cvt.rna.tf32.f32 %0, %1;" : "=r"(r) : "f"(f));
    return r;
}

__global__ __launch_bounds__(128) void k_gemm1(const float* __restrict__ X,
                                               const float* __restrict__ W1,
                                               float* __restrict__ XW) {
    __shared__ float As[128][36];    // row-major X tile, pad->bank (4m+k)%32 distinct
    __shared__ float Bs[32][136];    // row-major W1 tile, bank (8k+n)%32 distinct

    const int tid  = threadIdx.x;
    const int lane = tid & 31;
    const int wid  = tid >> 5;
    const int wm   = wid & 1;        // warp row (0..1) -> 64 rows
    const int wn   = wid >> 1;       // warp col (0..1) -> 64 cols
    const int gid  = lane >> 2;      // 0..7
    const int tig  = lane & 3;       // 0..3

    const int m0 = blockIdx.x * 128;
    const int n0 = blockIdx.y * 128;

    float acc[4][8][4];
#pragma unroll
    for (int mf = 0; mf < 4; mf++)
#pragma unroll
        for (int nf = 0; nf < 8; nf++)
#pragma unroll
            for (int c = 0; c < 4; c++) acc[mf][nf][c] = 0.f;

    for (int k0 = 0; k0 < NF; k0 += 32) {
        // stage A tile: 128 rows x 32 cols  (coalesced: 8 lanes cover 128B of a row)
#pragma unroll
        for (int p = 0; p < 8; p++) {
            int i = p * 128 + tid;
            int m = i >> 3, j = i & 7;
            int row = m0 + m;
            row = row < NN ? row : NN - 1;      // clamp; OOB rows never stored
            float4 v = *(const float4*)(X + (size_t)row * NF + k0 + j * 4);
            float4 w;
            w.x = __uint_as_float(f2tf32(v.x));
            w.y = __uint_as_float(f2tf32(v.y));
            w.z = __uint_as_float(f2tf32(v.z));
            w.w = __uint_as_float(f2tf32(v.w));
            *(float4*)&As[m][j * 4] = w;
        }
        // stage B tile: 32 rows x 128 cols (fully coalesced)
#pragma unroll
        for (int p = 0; p < 8; p++) {
            int i = p * 128 + tid;
            int k = i >> 5, j = i & 31;
            float4 v = *(const float4*)(W1 + (size_t)(k0 + k) * NH + n0 + j * 4);
            float4 w;
            w.x = __uint_as_float(f2tf32(v.x));
            w.y = __uint_as_float(f2tf32(v.y));
            w.z = __uint_as_float(f2tf32(v.z));
            w.w = __uint_as_float(f2tf32(v.w));
            *(float4*)&Bs[k][j * 4] = w;
        }
        __syncthreads();

#pragma unroll
        for (int ks = 0; ks < 4; ks++) {
            uint32_t a[4][4];
#pragma unroll
            for (int mf = 0; mf < 4; mf++) {
                int mm = wm * 64 + mf * 16 + gid;
                int kk = ks * 8 + tig;
                a[mf][0] = __float_as_uint(As[mm    ][kk    ]);
                a[mf][1] = __float_as_uint(As[mm + 8][kk    ]);
                a[mf][2] = __float_as_uint(As[mm    ][kk + 4]);
                a[mf][3] = __float_as_uint(As[mm + 8][kk + 4]);
            }
#pragma unroll
            for (int nf = 0; nf < 8; nf++) {
                int nn = wn * 64 + nf * 8 + gid;
                uint32_t b0 = __float_as_uint(Bs[ks * 8 + tig    ][nn]);
                uint32_t b1 = __float_as_uint(Bs[ks * 8 + tig + 4][nn]);
#pragma unroll
                for (int mf = 0; mf < 4; mf++) {
                    asm volatile(
                        "mma.sync.aligned.m16n8k8.row.col.f32.tf32.tf32.f32 "
                        "{%0,%1,%2,%3}, {%4,%5,%6,%7}, {%8,%9}, {%0,%1,%2,%3};\n"
                        : "+f"(acc[mf][nf][0]), "+f"(acc[mf][nf][1]),
                          "+f"(acc[mf][nf][2]), "+f"(acc[mf][nf][3])
                        : "r"(a[mf][0]), "r"(a[mf][1]), "r"(a[mf][2]), "r"(a[mf][3]),
                          "r"(b0), "r"(b1));
                }
            }
        }
        __syncthreads();
    }

    // epilogue: c0 (gid, 2tig), c1 (gid, 2tig+1), c2 (gid+8, 2tig), c3 (gid+8, 2tig+1)
#pragma unroll
    for (int mf = 0; mf < 4; mf++) {
#pragma unroll
        for (int nf = 0; nf < 8; nf++) {
            int row = m0 + wm * 64 + mf * 16 + gid;
            int col = n0 + wn * 64 + nf * 8 + 2 * tig;
            if (row < NN) {
                float2 v0 = make_float2(acc[mf][nf][0], acc[mf][nf][1]);
                *(float2*)(XW + (size_t)row * NH + col) = v0;
            }
            if (row + 8 < NN) {
                float2 v1 = make_float2(acc[mf][nf][2], acc[mf][nf][3]);
                *(float2*)(XW + (size_t)(row + 8) * NH + col) = v1;
            }
        }
    }
}

// ---------------- SpMM1: H = relu(A @ XW + b1), warp per row ----------------
__global__ __launch_bounds__(256) void k_spmm1(const float* __restrict__ XW,
                                               const float* __restrict__ b1,
                                               float* __restrict__ H) {
    int w = (blockIdx.x * blockDim.x + threadIdx.x) >> 5;
    int lane = threadIdx.x & 31;
    if (w >= NN) return;
    int s = d_rowptr[w], e = d_rowptr[w + 1];
    float4 a0 = make_float4(0.f, 0.f, 0.f, 0.f);
    float4 a1 = make_float4(0.f, 0.f, 0.f, 0.f);
    for (int i = s; i < e; i++) {
        int c = d_ccol[i];
        float v = d_cval[i];
        const float4* p = (const float4*)(XW + (size_t)c * NH);
        float4 x0 = p[lane];
        float4 x1 = p[lane + 32];
        a0.x += v * x0.x; a0.y += v * x0.y; a0.z += v * x0.z; a0.w += v * x0.w;
        a1.x += v * x1.x; a1.y += v * x1.y; a1.z += v * x1.z; a1.w += v * x1.w;
    }
    const float4* bb = (const float4*)b1;
    float4 c0 = bb[lane], c1 = bb[lane + 32];
    a0.x = fmaxf(a0.x + c0.x, 0.f); a0.y = fmaxf(a0.y + c0.y, 0.f);
    a0.z = fmaxf(a0.z + c0.z, 0.f); a0.w = fmaxf(a0.w + c0.w, 0.f);
    a1.x = fmaxf(a1.x + c1.x, 0.f); a1.y = fmaxf(a1.y + c1.y, 0.f);
    a1.z = fmaxf(a1.z + c1.z, 0.f); a1.w = fmaxf(a1.w + c1.w, 0.f);
    float4* hp = (float4*)(H + (size_t)w * NH);
    hp[lane]      = a0;
    hp[lane + 32] = a1;
}

// ---------------- GEMM2: HW = H @ W2 ----------------
__global__ __launch_bounds__(256) void k_gemm2(const float* __restrict__ H,
                                               const float* __restrict__ W2,
                                               float* __restrict__ HW) {
    __shared__ float w2s[NH * NC];   // 40 KB
    for (int i = threadIdx.x; i < NH * NC; i += 256) w2s[i] = W2[i];
    __syncthreads();
    int r = blockIdx.x * 256 + threadIdx.x;
    if (r >= NN) return;
    float acc[NC];
#pragma unroll
    for (int c = 0; c < NC; c++) acc[c] = 0.f;
    const float4* hp = (const float4*)(H + (size_t)r * NH);
#pragma unroll 4
    for (int k4 = 0; k4 < NH / 4; k4++) {
        float4 h = hp[k4];
        float hv[4] = {h.x, h.y, h.z, h.w};
#pragma unroll
        for (int kk = 0; kk < 4; kk++) {
            const float* wrow = &w2s[(k4 * 4 + kk) * NC];
#pragma unroll
            for (int c4 = 0; c4 < NC / 4; c4++) {
                float4 wv = *(const float4*)(wrow + c4 * 4);
                acc[c4 * 4 + 0] += hv[kk] * wv.x;
                acc[c4 * 4 + 1] += hv[kk] * wv.y;
                acc[c4 * 4 + 2] += hv[kk] * wv.z;
                acc[c4 * 4 + 3] += hv[kk] * wv.w;
            }
        }
    }
    float* o = HW + (size_t)r * NC;
#pragma unroll
    for (int c4 = 0; c4 < NC / 4; c4++)
        *(float4*)(o + c4 * 4) = make_float4(acc[c4 * 4], acc[c4 * 4 + 1],
                                             acc[c4 * 4 + 2], acc[c4 * 4 + 3]);
}

// ---------------- SpMM2: out = A @ HW + b2, warp per row ----------------
__global__ __launch_bounds__(256) void k_spmm2(const float* __restrict__ HW,
                                               const float* __restrict__ b2,
                                               float* __restrict__ out) {
    int w = (blockIdx.x * blockDim.x + threadIdx.x) >> 5;
    int lane = threadIdx.x & 31;
    if (w >= NN) return;
    int s = d_rowptr[w], e = d_rowptr[w + 1];
    float a0 = 0.f, a1 = 0.f;
    for (int i = s; i < e; i++) {
        int c = d_ccol[i];
        float v = d_cval[i];
        const float* p = HW + (size_t)c * NC;
        a0 += v * p[lane];
        if (lane < 8) a1 += v * p[lane + 32];
    }
    float* o = out + (size_t)w * NC;
    o[lane] = a0 + b2[lane];
    if (lane < 8) o[lane + 32] = a1 + b2[lane + 32];
}

// ---------------- launch ----------------
extern "C" void kernel_launch(void* const* d_in, const int* in_sizes, int n_in,
                              void* d_out, int out_size) {
    const float* x   = (const float*)d_in[0];
    const float* W1  = (const float*)d_in[1];
    const float* b1  = (const float*)d_in[2];
    const float* W2  = (const float*)d_in[3];
    const float* b2  = (const float*)d_in[4];
    const int*   er  = (const int*)d_in[5];
    const int*   ec  = (const int*)d_in[6];
    const float* ev  = (const float*)d_in[7];
    int E = in_sizes[5];
    if (E > ECAP) E = ECAP;
    float* out = (float*)d_out;

    void *degp, *curp;
    cudaGetSymbolAddress(&degp, d_deg);
    cudaGetSymbolAddress(&curp, d_cursor);
    cudaMemsetAsync(degp, 0, NN * sizeof(int));
    cudaMemsetAsync(curp, 0, NN * sizeof(int));

    k_hist<<<(E + 511) / 512, 512>>>(er, E);
    int nb = (NN + 511) / 512;   // 196
    k_scan1<<<nb, 512>>>();
    k_scan2<<<1, 256>>>(nb);

    // gemm1 is the 6th launch (2 memsets + hist + scan1 + scan2 before it)
    // so ncu -s 5 -c 1 profiles it. It is independent of scan3/scatter.
    dim3 g1((NN + 127) / 128, NH / 128);
    k_gemm1<<<g1, 128>>>(x, W1, d_XW);

    k_scan3<<<nb, 512>>>(E);
    k_scatter<<<(E + 255) / 256, 256>>>(er, ec, ev, E);

    k_spmm1<<<(NN * 32 + 255) / 256, 256>>>(d_XW, b1, d_H);
    k_gemm2<<<(NN + 255) / 256, 256>>>(d_H, W2, d_HW);
    k_spmm2<<<(NN * 32 + 255) / 256, 256>>>(d_HW, b2, out);
}